// round 13
// baseline (speedup 1.0000x reference)
#include <cuda_runtime.h>
#include <cuda_fp16.h>
#include <math.h>
#include <stdint.h>

#define BATCH   32
#define SEQ     4096
#define C_IN    7
#define NF      35
#define D_MODEL 512
#define WINDOW  24
#define KDIM    105
#define FW      40           // F row width in halfs (80B, 16B-aligned)
#define FWU     20           // F row width in u32
#define LDW     128          // W row width in halfs (K = 128, 8 k16 steps)
// F row = [35 feats | 5 zeros].  A row for output s = 120 contiguous halfs of
// g_F starting at (s-1)*40 (circular in s):  F[s-1] | F[s] | F[s+1].
// W col k: tap = k/40, i = k%40; real iff tap<3 && i<35, else zero.

// Compact padded fp16 feature rows: [BATCH*SEQ][40]
__device__ __align__(16) __half g_F[(size_t)BATCH * SEQ * FW];
// W reordered/padded fp16: [D_MODEL][128]
__device__ __align__(16) __half g_Wh[D_MODEL * LDW];

// ---------------------------------------------------------------------------
// Phase 1 (fused): rolling stats -> g_F;  W prep on the extra y-slice.
// ---------------------------------------------------------------------------
#define P1_TS 256
#define WPREP_BLOCKS ((D_MODEL * LDW) / P1_TS)   // 256
#define FST 21                                   // staging row stride (u32), coprime 32

__global__ __launch_bounds__(P1_TS) void stats_kernel(const float* __restrict__ x,
                                                      const float* __restrict__ Wg) {
    const int tid = threadIdx.x;

    if (blockIdx.y == BATCH) {
        // W prep: col k -> tap = k/40, i = k%40
        int idx = blockIdx.x * P1_TS + tid;
        int n = idx / LDW, k = idx - n * LDW;
        int tap = k / FW, i = k - tap * FW;
        float v = 0.0f;
        if (tap < 3 && i < NF) v = Wg[(size_t)n * KDIM + i * 3 + tap];
        g_Wh[idx] = __float2half(v);
        return;
    }
    if (blockIdx.x >= SEQ / P1_TS) return;

    __shared__ uint32_t fst[P1_TS * FST];                    // 21504 B
    __shared__ float sx[(P1_TS + WINDOW - 1) * C_IN];        //  7812 B

    const int b   = blockIdx.y;
    const int s0  = blockIdx.x * P1_TS;
    const float* xb = x + (size_t)b * SEQ * C_IN;

    for (int idx = tid; idx < (P1_TS + WINDOW - 1) * C_IN; idx += P1_TS) {
        int sg = s0 - (WINDOW - 1) + idx / C_IN;
        int c  = idx % C_IN;
        if (sg < 0) sg = 0;
        sx[idx] = xb[(size_t)sg * C_IN + c];
    }
    __syncthreads();

    float f[NF];
    #pragma unroll
    for (int c = 0; c < C_IN; c++) {
        float sum = 0.0f, mx = -3.0e38f, mn = 3.0e38f;
        #pragma unroll
        for (int t = 0; t < WINDOW; t++) {
            float v = sx[(tid + t) * C_IN + c];
            sum += v; mx = fmaxf(mx, v); mn = fminf(mn, v);
        }
        float mean = sum * (1.0f / WINDOW);
        float s2 = 0.0f;
        #pragma unroll
        for (int t = 0; t < WINDOW; t++) {
            float d = sx[(tid + t) * C_IN + c] - mean;
            s2 += d * d;
        }
        f[c]      = sx[(tid + WINDOW - 1) * C_IN + c];
        f[7 + c]  = mean;
        f[14 + c] = mx;
        f[21 + c] = mn;
        f[28 + c] = sqrtf(s2 * (1.0f / (WINDOW - 1)) + 1e-12f);
    }

    // pack & stage own row (stride 21 u32, coprime with 32 -> conflict-free)
    uint32_t* my = fst + tid * FST;
    #pragma unroll
    for (int i = 0; i < 17; i++) {
        __half2 h = __floats2half2_rn(f[2 * i], f[2 * i + 1]);
        my[i] = *(uint32_t*)&h;
    }
    {
        __half h = __float2half(f[34]);
        my[17] = (uint32_t)*(uint16_t*)&h;     // half 35 = 0
    }
    my[18] = 0; my[19] = 0;                    // halfs 36..39 = 0
    __syncthreads();

    // coalesced write: 256 rows x 20 u32 contiguous
    uint32_t* dst = (uint32_t*)g_F + ((size_t)b * SEQ + s0) * FWU;
    for (int idx = tid; idx < P1_TS * FWU; idx += P1_TS) {
        int r = idx / FWU, c = idx - r * FWU;
        dst[idx] = fst[r * FST + c];
    }
}

// ---------------------------------------------------------------------------
// Phase 2: fp16 mma.sync GEMM, full fp16 accumulation chain, K=128.
// CTA 64(M) x 128(N), 8 warps (2M x 4N), warp 32x32, 4 CTAs/SM.
// A = sliding-window view of 67 contiguous F rows (stride 40 halfs, 16B-ok).
// ---------------------------------------------------------------------------
#define BM 64
#define BN 128
#define CTH 256
#define FROWS 67
#define SF_U32 (FROWS * FWU + 4)                 // 1344 u32
#define SMEMB (SF_U32 * 4 + BN * LDW * 2 + BN * 4)   // 5376+32768+512 = 38656

__device__ __forceinline__ uint32_t smem_u32(const void* p) {
    uint32_t a;
    asm("{ .reg .u64 t; cvta.to.shared.u64 t, %1; cvt.u32.u64 %0, t; }" : "=r"(a) : "l"(p));
    return a;
}

__global__ __launch_bounds__(CTH, 4) void mma_kernel(const float* __restrict__ bias,
                                                     float* __restrict__ out) {
    extern __shared__ char smem[];
    uint32_t* sF  = (uint32_t*)smem;                     // 67 F-rows (20 u32 each)
    __half* sB    = (__half*)(smem + SF_U32 * 4);        // [BN][LDW]
    float*  sBias = (float*)(smem + SF_U32 * 4 + BN * LDW * 2);

    const int tid = threadIdx.x;
    const int mt  = blockIdx.x;               // 2048 M-tiles
    const int b   = mt >> 6;
    const int s0  = (mt & 63) * BM;
    const int n0  = blockIdx.y * BN;

    // ---- A: contiguous circular copy of g_F rows s0-1 .. s0+65 ----
    {
        const uint32_t* Fu = (const uint32_t*)g_F + (size_t)b * SEQ * FWU;
        const int span = SEQ * FWU;            // 81920
        int base = (s0 - 1) * FWU;             // may be -20 (tile 0)
        for (int idx = tid; idx < FROWS * FWU; idx += CTH) {
            int lin = base + idx;
            if (lin < 0) lin += span;
            else if (lin >= span) lin -= span;
            sF[idx] = Fu[lin];
        }
        if (tid < 4) sF[FROWS * FWU + tid] = 0;
    }
    // ---- B: contiguous uint4 copy of W tile (32 KB) ----
    {
        const uint4* src = (const uint4*)(g_Wh + (size_t)n0 * LDW);
        uint4* dst = (uint4*)sB;
        for (int i = tid; i < BN * LDW * 2 / 16; i += CTH) dst[i] = src[i];
    }
    if (tid < BN) sBias[tid] = bias[n0 + tid];
    __syncthreads();

    const int lane = tid & 31, w = tid >> 5;
    const int g = lane >> 2, q = lane & 3;
    const int mw = (w & 1) * 32;              // 2 warps along M
    const int nw = (w >> 1) * 32;             // 4 warps along N

    const uint32_t saBase = smem_u32(sF);
    const uint32_t sbBase = smem_u32(sB);
    // A row m starts at half m*40 (row 0 = F[s0-1] = window of output s0)
    const uint32_t aAddr = saBase +
        2u * ((uint32_t)(mw + (lane & 15)) * FW + ((lane >> 4) << 3));
    const uint32_t bt = lane >> 3, bj = lane & 7;
    const uint32_t bAddr = sbBase +
        2u * ((uint32_t)(nw + ((bt >> 1) << 3) + bj) * LDW + ((bt & 1) << 3));

    uint32_t d[2][4][2];
    #pragma unroll
    for (int mi = 0; mi < 2; mi++)
        #pragma unroll
        for (int ni = 0; ni < 4; ni++)
            d[mi][ni][0] = d[mi][ni][1] = 0u;

    #pragma unroll
    for (int ks = 0; ks < 8; ks++) {
        const uint32_t kOff = (uint32_t)ks * 32;   // bytes (16 halfs)

        uint32_t bf[4][2];
        #pragma unroll
        for (int nset = 0; nset < 2; nset++) {
            uint32_t ba = bAddr + kOff + (uint32_t)(nset * 16 * LDW * 2);
            asm volatile(
                "ldmatrix.sync.aligned.m8n8.x4.shared.b16 {%0,%1,%2,%3}, [%4];"
                : "=r"(bf[2 * nset][0]),     "=r"(bf[2 * nset][1]),
                  "=r"(bf[2 * nset + 1][0]), "=r"(bf[2 * nset + 1][1])
                : "r"(ba));
        }

        #pragma unroll
        for (int mi = 0; mi < 2; mi++) {
            uint32_t af[4];
            uint32_t aa = aAddr + (uint32_t)(2 * (mi * 16 * FW)) + kOff;
            asm volatile(
                "ldmatrix.sync.aligned.m8n8.x4.shared.b16 {%0,%1,%2,%3}, [%4];"
                : "=r"(af[0]), "=r"(af[1]), "=r"(af[2]), "=r"(af[3]) : "r"(aa));
            #pragma unroll
            for (int ni = 0; ni < 4; ni++)
                asm volatile(
                    "mma.sync.aligned.m16n8k16.row.col.f16.f16.f16.f16 "
                    "{%0,%1}, {%2,%3,%4,%5}, {%6,%7}, {%0,%1};"
                    : "+r"(d[mi][ni][0]), "+r"(d[mi][ni][1])
                    : "r"(af[0]), "r"(af[1]), "r"(af[2]), "r"(af[3]),
                      "r"(bf[ni][0]), "r"(bf[ni][1]));
        }
    }

    // ---- epilogue: f16 -> f32, bias, float2 stores ----
    #pragma unroll
    for (int mi = 0; mi < 2; mi++) {
        #pragma unroll
        for (int ni = 0; ni < 4; ni++) {
            const int colL = nw + ni * 8 + 2 * q;
            const float bx = sBias[colL], by = sBias[colL + 1];
            const size_t r1 = (size_t)mt * BM + mw + mi * 16 + g;
            float* p = out + r1 * D_MODEL + n0 + colL;
            float2 lo = __half22float2(*(__half2*)&d[mi][ni][0]);
            float2 hi = __half22float2(*(__half2*)&d[mi][ni][1]);
            float2 v0 = { lo.x + bx, lo.y + by };
            float2 v1 = { hi.x + bx, hi.y + by };
            *(float2*)p = v0;
            *(float2*)(p + 8 * D_MODEL) = v1;
        }
    }
}

// ---------------------------------------------------------------------------
extern "C" void kernel_launch(void* const* d_in, const int* in_sizes, int n_in,
                              void* d_out, int out_size) {
    const float* x = nullptr; const float* Wg = nullptr; const float* bias = nullptr;
    for (int i = 0; i < n_in; i++) {
        if (in_sizes[i] == BATCH * SEQ * C_IN)   x    = (const float*)d_in[i];
        else if (in_sizes[i] == D_MODEL * KDIM)  Wg   = (const float*)d_in[i];
        else if (in_sizes[i] == D_MODEL)         bias = (const float*)d_in[i];
        // x_mark (BATCH*SEQ*4) unused by the reference math
    }
    float* out = (float*)d_out;

    dim3 g1(WPREP_BLOCKS, BATCH + 1);
    stats_kernel<<<g1, P1_TS>>>(x, Wg);

    cudaFuncSetAttribute(mma_kernel, cudaFuncAttributeMaxDynamicSharedMemorySize, SMEMB);
    dim3 g2((BATCH * SEQ) / BM, D_MODEL / BN, 1);
    mma_kernel<<<g2, CTH, SMEMB>>>(bias, out);
}

// round 14
// speedup vs baseline: 1.7343x; 1.7343x over previous
#include <cuda_runtime.h>
#include <cuda_fp16.h>
#include <math.h>
#include <stdint.h>

#define BATCH   32
#define SEQ     4096
#define C_IN    7
#define NF      35
#define D_MODEL 512
#define WINDOW  24
#define KDIM    105
#define FW      40           // F row width in halfs (80B, 16B-aligned)
#define FWU     20           // F row width in u32
#define LDW     128          // W row width in halfs in GMEM (K = 128, 8 k16 steps)
#define SLB     136          // W row stride in SMEM halfs (272B: conflict-free LDSM)
// F row = [35 feats | 5 zeros].  A row for output s = 120 contiguous halfs of
// g_F starting at (s-1)*40 (circular in s):  F[s-1] | F[s] | F[s+1].
// W col k: tap = k/40, i = k%40; real iff tap<3 && i<35, else zero.
// (8th k-step cols 120..127 are W-zero; A reads there spill into the next
//  F row's storage — finite data annihilated by the zeros.)

// Compact padded fp16 feature rows: [BATCH*SEQ][40]
__device__ __align__(16) __half g_F[(size_t)BATCH * SEQ * FW];
// W reordered/padded fp16: [D_MODEL][128]
__device__ __align__(16) __half g_Wh[D_MODEL * LDW];

// ---------------------------------------------------------------------------
// Phase 1 (fused): rolling stats -> g_F;  W prep on the extra y-slice.
// ---------------------------------------------------------------------------
#define P1_TS 256
#define WPREP_BLOCKS ((D_MODEL * LDW) / P1_TS)   // 256
#define FST 21                                   // staging row stride (u32), coprime 32

__global__ __launch_bounds__(P1_TS) void stats_kernel(const float* __restrict__ x,
                                                      const float* __restrict__ Wg) {
    const int tid = threadIdx.x;

    if (blockIdx.y == BATCH) {
        // W prep: col k -> tap = k/40, i = k%40
        int idx = blockIdx.x * P1_TS + tid;
        int n = idx / LDW, k = idx - n * LDW;
        int tap = k / FW, i = k - tap * FW;
        float v = 0.0f;
        if (tap < 3 && i < NF) v = Wg[(size_t)n * KDIM + i * 3 + tap];
        g_Wh[idx] = __float2half(v);
        return;
    }
    if (blockIdx.x >= SEQ / P1_TS) return;

    __shared__ uint32_t fst[P1_TS * FST];                    // 21504 B
    __shared__ float sx[(P1_TS + WINDOW - 1) * C_IN];        //  7812 B

    const int b   = blockIdx.y;
    const int s0  = blockIdx.x * P1_TS;
    const float* xb = x + (size_t)b * SEQ * C_IN;

    for (int idx = tid; idx < (P1_TS + WINDOW - 1) * C_IN; idx += P1_TS) {
        int sg = s0 - (WINDOW - 1) + idx / C_IN;
        int c  = idx % C_IN;
        if (sg < 0) sg = 0;
        sx[idx] = xb[(size_t)sg * C_IN + c];
    }
    __syncthreads();

    float f[NF];
    #pragma unroll
    for (int c = 0; c < C_IN; c++) {
        float sum = 0.0f, mx = -3.0e38f, mn = 3.0e38f;
        #pragma unroll
        for (int t = 0; t < WINDOW; t++) {
            float v = sx[(tid + t) * C_IN + c];
            sum += v; mx = fmaxf(mx, v); mn = fminf(mn, v);
        }
        float mean = sum * (1.0f / WINDOW);
        float s2 = 0.0f;
        #pragma unroll
        for (int t = 0; t < WINDOW; t++) {
            float d = sx[(tid + t) * C_IN + c] - mean;
            s2 += d * d;
        }
        f[c]      = sx[(tid + WINDOW - 1) * C_IN + c];
        f[7 + c]  = mean;
        f[14 + c] = mx;
        f[21 + c] = mn;
        f[28 + c] = sqrtf(s2 * (1.0f / (WINDOW - 1)) + 1e-12f);
    }

    // pack & stage own row (stride 21 u32, coprime with 32 -> conflict-free)
    uint32_t* my = fst + tid * FST;
    #pragma unroll
    for (int i = 0; i < 17; i++) {
        __half2 h = __floats2half2_rn(f[2 * i], f[2 * i + 1]);
        my[i] = *(uint32_t*)&h;
    }
    {
        __half h = __float2half(f[34]);
        my[17] = (uint32_t)*(uint16_t*)&h;     // half 35 = 0
    }
    my[18] = 0; my[19] = 0;                    // halfs 36..39 = 0
    __syncthreads();

    // coalesced write: 256 rows x 20 u32 contiguous
    uint32_t* dst = (uint32_t*)g_F + ((size_t)b * SEQ + s0) * FWU;
    for (int idx = tid; idx < P1_TS * FWU; idx += P1_TS) {
        int r = idx / FWU, c = idx - r * FWU;
        dst[idx] = fst[r * FST + c];
    }
}

// ---------------------------------------------------------------------------
// Phase 2: fp16 mma.sync GEMM, full fp16 accumulation chain, K=128.
// CTA 64(M) x 128(N), 8 warps (2M x 4N), warp 32x32, 4 CTAs/SM.
// A = sliding-window view of 67 contiguous F rows (stride 40 halfs).
// B staged at 136-half stride (conflict-free LDSM).
// ---------------------------------------------------------------------------
#define BM 64
#define BN 128
#define CTH 256
#define FROWS 67
#define SF_U32 (FROWS * FWU + 4)                 // 1344 u32
#define SMEMB (SF_U32 * 4 + BN * SLB * 2 + BN * 4)   // 5376+34816+512 = 40704

__device__ __forceinline__ uint32_t smem_u32(const void* p) {
    uint32_t a;
    asm("{ .reg .u64 t; cvta.to.shared.u64 t, %1; cvt.u32.u64 %0, t; }" : "=r"(a) : "l"(p));
    return a;
}

__global__ __launch_bounds__(CTH, 4) void mma_kernel(const float* __restrict__ bias,
                                                     float* __restrict__ out) {
    extern __shared__ char smem[];
    uint32_t* sF  = (uint32_t*)smem;                     // 67 F-rows (20 u32 each)
    __half* sB    = (__half*)(smem + SF_U32 * 4);        // [BN][SLB]
    float*  sBias = (float*)(smem + SF_U32 * 4 + BN * SLB * 2);

    const int tid = threadIdx.x;
    const int mt  = blockIdx.x;               // 2048 M-tiles
    const int b   = mt >> 6;
    const int s0  = (mt & 63) * BM;
    const int n0  = blockIdx.y * BN;

    // ---- A: contiguous circular copy of g_F rows s0-1 .. s0+65 ----
    {
        const uint32_t* Fu = (const uint32_t*)g_F + (size_t)b * SEQ * FWU;
        const int span = SEQ * FWU;            // 81920
        int base = (s0 - 1) * FWU;             // may be -20 (tile 0)
        for (int idx = tid; idx < FROWS * FWU; idx += CTH) {
            int lin = base + idx;
            if (lin < 0) lin += span;
            else if (lin >= span) lin -= span;
            sF[idx] = Fu[lin];
        }
        if (tid < 4) sF[FROWS * FWU + tid] = 0;
    }
    // ---- B: uint4 copy of W tile into 136-half-stride rows ----
    {
        const uint4* src = (const uint4*)(g_Wh + (size_t)n0 * LDW);
        for (int idx = tid; idx < BN * (LDW / 8); idx += CTH) {
            int r = idx >> 4, c = idx & 15;            // 16 uint4 per row
            *(uint4*)(sB + r * SLB + c * 8) = src[idx];
        }
    }
    if (tid < BN) sBias[tid] = bias[n0 + tid];
    __syncthreads();

    const int lane = tid & 31, w = tid >> 5;
    const int g = lane >> 2, q = lane & 3;
    const int mw = (w & 1) * 32;              // 2 warps along M
    const int nw = (w >> 1) * 32;             // 4 warps along N

    const uint32_t saBase = smem_u32(sF);
    const uint32_t sbBase = smem_u32(sB);
    // A row m starts at half m*40 (row 0 = F[s0-1] = window of output s0)
    const uint32_t aAddr = saBase +
        2u * ((uint32_t)(mw + (lane & 15)) * FW + ((lane >> 4) << 3));
    const uint32_t bt = lane >> 3, bj = lane & 7;
    const uint32_t bAddr = sbBase +
        2u * ((uint32_t)(nw + ((bt >> 1) << 3) + bj) * SLB + ((bt & 1) << 3));

    uint32_t d[2][4][2];
    #pragma unroll
    for (int mi = 0; mi < 2; mi++)
        #pragma unroll
        for (int ni = 0; ni < 4; ni++)
            d[mi][ni][0] = d[mi][ni][1] = 0u;

    #pragma unroll
    for (int ks = 0; ks < 8; ks++) {
        const uint32_t kOff = (uint32_t)ks * 32;   // bytes (16 halfs)

        uint32_t bf[4][2];
        #pragma unroll
        for (int nset = 0; nset < 2; nset++) {
            uint32_t ba = bAddr + kOff + (uint32_t)(nset * 16 * SLB * 2);
            asm volatile(
                "ldmatrix.sync.aligned.m8n8.x4.shared.b16 {%0,%1,%2,%3}, [%4];"
                : "=r"(bf[2 * nset][0]),     "=r"(bf[2 * nset][1]),
                  "=r"(bf[2 * nset + 1][0]), "=r"(bf[2 * nset + 1][1])
                : "r"(ba));
        }

        #pragma unroll
        for (int mi = 0; mi < 2; mi++) {
            uint32_t af[4];
            uint32_t aa = aAddr + (uint32_t)(2 * (mi * 16 * FW)) + kOff;
            asm volatile(
                "ldmatrix.sync.aligned.m8n8.x4.shared.b16 {%0,%1,%2,%3}, [%4];"
                : "=r"(af[0]), "=r"(af[1]), "=r"(af[2]), "=r"(af[3]) : "r"(aa));
            #pragma unroll
            for (int ni = 0; ni < 4; ni++)
                asm volatile(
                    "mma.sync.aligned.m16n8k16.row.col.f16.f16.f16.f16 "
                    "{%0,%1}, {%2,%3,%4,%5}, {%6,%7}, {%0,%1};"
                    : "+r"(d[mi][ni][0]), "+r"(d[mi][ni][1])
                    : "r"(af[0]), "r"(af[1]), "r"(af[2]), "r"(af[3]),
                      "r"(bf[ni][0]), "r"(bf[ni][1]));
        }
    }

    // ---- epilogue: f16 -> f32, bias, float2 stores ----
    #pragma unroll
    for (int mi = 0; mi < 2; mi++) {
        #pragma unroll
        for (int ni = 0; ni < 4; ni++) {
            const int colL = nw + ni * 8 + 2 * q;
            const float bx = sBias[colL], by = sBias[colL + 1];
            const size_t r1 = (size_t)mt * BM + mw + mi * 16 + g;
            float* p = out + r1 * D_MODEL + n0 + colL;
            float2 lo = __half22float2(*(__half2*)&d[mi][ni][0]);
            float2 hi = __half22float2(*(__half2*)&d[mi][ni][1]);
            float2 v0 = { lo.x + bx, lo.y + by };
            float2 v1 = { hi.x + bx, hi.y + by };
            *(float2*)p = v0;
            *(float2*)(p + 8 * D_MODEL) = v1;
        }
    }
}

// ---------------------------------------------------------------------------
extern "C" void kernel_launch(void* const* d_in, const int* in_sizes, int n_in,
                              void* d_out, int out_size) {
    const float* x = nullptr; const float* Wg = nullptr; const float* bias = nullptr;
    for (int i = 0; i < n_in; i++) {
        if (in_sizes[i] == BATCH * SEQ * C_IN)   x    = (const float*)d_in[i];
        else if (in_sizes[i] == D_MODEL * KDIM)  Wg   = (const float*)d_in[i];
        else if (in_sizes[i] == D_MODEL)         bias = (const float*)d_in[i];
        // x_mark (BATCH*SEQ*4) unused by the reference math
    }
    float* out = (float*)d_out;

    dim3 g1(WPREP_BLOCKS, BATCH + 1);
    stats_kernel<<<g1, P1_TS>>>(x, Wg);

    cudaFuncSetAttribute(mma_kernel, cudaFuncAttributeMaxDynamicSharedMemorySize, SMEMB);
    dim3 g2((BATCH * SEQ) / BM, D_MODEL / BN, 1);
    mma_kernel<<<g2, CTH, SMEMB>>>(bias, out);
}

// round 15
// speedup vs baseline: 1.8436x; 1.0630x over previous
#include <cuda_runtime.h>
#include <cuda_fp16.h>
#include <math.h>
#include <stdint.h>

#define BATCH   32
#define SEQ     4096
#define C_IN    7
#define NF      35
#define D_MODEL 512
#define WINDOW  24
#define KDIM    105
#define FW      40           // F row width in halfs (80B, 16B-aligned)
#define FWU     20           // F row width in u32
#define LDW     128          // W row width in halfs in GMEM (K = 128, 8 k16 steps)
#define SLB     136          // W row stride in SMEM halfs (272B: conflict-free LDSM)
// F row = [35 feats | 5 zeros].  A row for output s = 120 contiguous halfs of
// g_F starting at (s-1)*40 (circular in s):  F[s-1] | F[s] | F[s+1].
// W col k: tap = k/40, i = k%40; real iff tap<3 && i<35, else zero.

// Compact padded fp16 feature rows: [BATCH*SEQ][40]
__device__ __align__(16) __half g_F[(size_t)BATCH * SEQ * FW];
// W reordered/padded fp16: [D_MODEL][128]
__device__ __align__(16) __half g_Wh[D_MODEL * LDW];

// ---------------------------------------------------------------------------
// Phase 1 (fused): rolling stats -> g_F;  W prep on the extra y-slice.
// ---------------------------------------------------------------------------
#define P1_TS 256
#define WPREP_BLOCKS ((D_MODEL * LDW) / P1_TS)   // 256
#define FST 21                                   // staging row stride (u32), coprime 32

__global__ __launch_bounds__(P1_TS) void stats_kernel(const float* __restrict__ x,
                                                      const float* __restrict__ Wg) {
    const int tid = threadIdx.x;

    if (blockIdx.y == BATCH) {
        // W prep: col k -> tap = k/40, i = k%40
        int idx = blockIdx.x * P1_TS + tid;
        int n = idx / LDW, k = idx - n * LDW;
        int tap = k / FW, i = k - tap * FW;
        float v = 0.0f;
        if (tap < 3 && i < NF) v = Wg[(size_t)n * KDIM + i * 3 + tap];
        g_Wh[idx] = __float2half(v);
        return;
    }
    if (blockIdx.x >= SEQ / P1_TS) return;

    __shared__ uint32_t fst[P1_TS * FST];                    // 21504 B
    __shared__ float sx[(P1_TS + WINDOW - 1) * C_IN];        //  7812 B

    const int b   = blockIdx.y;
    const int s0  = blockIdx.x * P1_TS;
    const float* xb = x + (size_t)b * SEQ * C_IN;

    for (int idx = tid; idx < (P1_TS + WINDOW - 1) * C_IN; idx += P1_TS) {
        int sg = s0 - (WINDOW - 1) + idx / C_IN;
        int c  = idx % C_IN;
        if (sg < 0) sg = 0;
        sx[idx] = xb[(size_t)sg * C_IN + c];
    }
    __syncthreads();

    float f[NF];
    #pragma unroll
    for (int c = 0; c < C_IN; c++) {
        float sum = 0.0f, mx = -3.0e38f, mn = 3.0e38f;
        #pragma unroll
        for (int t = 0; t < WINDOW; t++) {
            float v = sx[(tid + t) * C_IN + c];
            sum += v; mx = fmaxf(mx, v); mn = fminf(mn, v);
        }
        float mean = sum * (1.0f / WINDOW);
        float s2 = 0.0f;
        #pragma unroll
        for (int t = 0; t < WINDOW; t++) {
            float d = sx[(tid + t) * C_IN + c] - mean;
            s2 += d * d;
        }
        f[c]      = sx[(tid + WINDOW - 1) * C_IN + c];
        f[7 + c]  = mean;
        f[14 + c] = mx;
        f[21 + c] = mn;
        f[28 + c] = sqrtf(s2 * (1.0f / (WINDOW - 1)) + 1e-12f);
    }

    // pack & stage own row (stride 21 u32, coprime with 32 -> conflict-free)
    uint32_t* my = fst + tid * FST;
    #pragma unroll
    for (int i = 0; i < 17; i++) {
        __half2 h = __floats2half2_rn(f[2 * i], f[2 * i + 1]);
        my[i] = *(uint32_t*)&h;
    }
    {
        __half h = __float2half(f[34]);
        my[17] = (uint32_t)*(uint16_t*)&h;     // half 35 = 0
    }
    my[18] = 0; my[19] = 0;                    // halfs 36..39 = 0
    __syncthreads();

    // coalesced write: 256 rows x 20 u32 contiguous
    uint32_t* dst = (uint32_t*)g_F + ((size_t)b * SEQ + s0) * FWU;
    for (int idx = tid; idx < P1_TS * FWU; idx += P1_TS) {
        int r = idx / FWU, c = idx - r * FWU;
        dst[idx] = fst[r * FST + c];
    }
}

// ---------------------------------------------------------------------------
// Phase 2: fp16 mma.sync GEMM, full fp16 accumulation chain, K=128.
// CTA 64(M) x 128(N), 8 warps (2M x 4N), warp 32x32, 4 CTAs/SM.
// A = sliding-window view of 67 contiguous F rows; B at 136-half stride.
// Staged f16 epilogue -> coalesced STG.128.
// ---------------------------------------------------------------------------
#define BM 64
#define BN 128
#define CTH 256
#define FROWS 67
#define SF_U32 (FROWS * FWU + 4)                 // 1344 u32
#define SMEMB (SF_U32 * 4 + BN * SLB * 2 + BN * 4)   // 5376+34816+512 = 40704
#define EST 68    // epilogue stage row stride (u32); 64 rows x 68 = 17408 B

__device__ __forceinline__ uint32_t smem_u32(const void* p) {
    uint32_t a;
    asm("{ .reg .u64 t; cvta.to.shared.u64 t, %1; cvt.u32.u64 %0, t; }" : "=r"(a) : "l"(p));
    return a;
}

__global__ __launch_bounds__(CTH, 4) void mma_kernel(const float* __restrict__ bias,
                                                     float* __restrict__ out) {
    extern __shared__ char smem[];
    uint32_t* sF  = (uint32_t*)smem;                     // 67 F-rows (20 u32 each)
    __half* sB    = (__half*)(smem + SF_U32 * 4);        // [BN][SLB]
    float*  sBias = (float*)(smem + SF_U32 * 4 + BN * SLB * 2);
    uint32_t* stage = (uint32_t*)smem;                   // reused post-mainloop

    const int tid = threadIdx.x;
    const int mt  = blockIdx.x;               // 2048 M-tiles
    const int b   = mt >> 6;
    const int s0  = (mt & 63) * BM;
    const int n0  = blockIdx.y * BN;

    // ---- A: contiguous circular copy of g_F rows s0-1 .. s0+65 ----
    {
        const uint32_t* Fu = (const uint32_t*)g_F + (size_t)b * SEQ * FWU;
        const int span = SEQ * FWU;            // 81920
        int base = (s0 - 1) * FWU;             // may be -20 (tile 0)
        for (int idx = tid; idx < FROWS * FWU; idx += CTH) {
            int lin = base + idx;
            if (lin < 0) lin += span;
            else if (lin >= span) lin -= span;
            sF[idx] = Fu[lin];
        }
        if (tid < 4) sF[FROWS * FWU + tid] = 0;
    }
    // ---- B: uint4 copy of W tile into 136-half-stride rows ----
    {
        const uint4* src = (const uint4*)(g_Wh + (size_t)n0 * LDW);
        for (int idx = tid; idx < BN * (LDW / 8); idx += CTH) {
            int r = idx >> 4, c = idx & 15;            // 16 uint4 per row
            *(uint4*)(sB + r * SLB + c * 8) = src[idx];
        }
    }
    if (tid < BN) sBias[tid] = bias[n0 + tid];
    __syncthreads();

    const int lane = tid & 31, w = tid >> 5;
    const int g = lane >> 2, q = lane & 3;
    const int mw = (w & 1) * 32;              // 2 warps along M
    const int nw = (w >> 1) * 32;             // 4 warps along N

    const uint32_t saBase = smem_u32(sF);
    const uint32_t sbBase = smem_u32(sB);
    const uint32_t aAddr = saBase +
        2u * ((uint32_t)(mw + (lane & 15)) * FW + ((lane >> 4) << 3));
    const uint32_t bt = lane >> 3, bj = lane & 7;
    const uint32_t bAddr = sbBase +
        2u * ((uint32_t)(nw + ((bt >> 1) << 3) + bj) * SLB + ((bt & 1) << 3));

    uint32_t d[2][4][2];
    #pragma unroll
    for (int mi = 0; mi < 2; mi++)
        #pragma unroll
        for (int ni = 0; ni < 4; ni++)
            d[mi][ni][0] = d[mi][ni][1] = 0u;

    #pragma unroll
    for (int ks = 0; ks < 8; ks++) {
        const uint32_t kOff = (uint32_t)ks * 32;   // bytes (16 halfs)

        uint32_t bf[4][2];
        #pragma unroll
        for (int nset = 0; nset < 2; nset++) {
            uint32_t ba = bAddr + kOff + (uint32_t)(nset * 16 * SLB * 2);
            asm volatile(
                "ldmatrix.sync.aligned.m8n8.x4.shared.b16 {%0,%1,%2,%3}, [%4];"
                : "=r"(bf[2 * nset][0]),     "=r"(bf[2 * nset][1]),
                  "=r"(bf[2 * nset + 1][0]), "=r"(bf[2 * nset + 1][1])
                : "r"(ba));
        }

        #pragma unroll
        for (int mi = 0; mi < 2; mi++) {
            uint32_t af[4];
            uint32_t aa = aAddr + (uint32_t)(2 * (mi * 16 * FW)) + kOff;
            asm volatile(
                "ldmatrix.sync.aligned.m8n8.x4.shared.b16 {%0,%1,%2,%3}, [%4];"
                : "=r"(af[0]), "=r"(af[1]), "=r"(af[2]), "=r"(af[3]) : "r"(aa));
            #pragma unroll
            for (int ni = 0; ni < 4; ni++)
                asm volatile(
                    "mma.sync.aligned.m16n8k16.row.col.f16.f16.f16.f16 "
                    "{%0,%1}, {%2,%3,%4,%5}, {%6,%7}, {%0,%1};"
                    : "+r"(d[mi][ni][0]), "+r"(d[mi][ni][1])
                    : "r"(af[0]), "r"(af[1]), "r"(af[2]), "r"(af[3]),
                      "r"(bf[ni][0]), "r"(bf[ni][1]));
        }
    }

    // ---- epilogue: stage f16 accumulators -> coalesced f32 stores ----
    float4 bv = *(const float4*)&sBias[lane * 4];   // this lane's 4 bias cols
    __syncthreads();                                // all LDSM done; reuse sF/sB

    // STS: addr = row*EST + colu;  lanes within an instr: (4g+q) mod 32 -> CF
    #pragma unroll
    for (int mi = 0; mi < 2; mi++)
        #pragma unroll
        for (int ni = 0; ni < 4; ni++) {
            uint32_t colu = (uint32_t)(nw / 2 + ni * 4 + q);
            uint32_t r0 = (uint32_t)(mw + mi * 16 + g);
            stage[r0 * EST + colu]       = d[mi][ni][0];
            stage[(r0 + 8) * EST + colu] = d[mi][ni][1];
        }
    __syncthreads();

    // 8 passes: warp w writes row p*8+w; lane covers 4 consecutive f32 cols
    float* obase = out + ((size_t)mt * BM) * D_MODEL + n0 + lane * 4;
    #pragma unroll
    for (int p = 0; p < 8; p++) {
        int row = p * 8 + w;
        uint2 pk = *(const uint2*)&stage[row * EST + lane * 2];
        float2 lo = __half22float2(*(__half2*)&pk.x);
        float2 hi = __half22float2(*(__half2*)&pk.y);
        float4 v = { lo.x + bv.x, lo.y + bv.y, hi.x + bv.z, hi.y + bv.w };
        *(float4*)(obase + (size_t)row * D_MODEL) = v;
    }
}

// ---------------------------------------------------------------------------
extern "C" void kernel_launch(void* const* d_in, const int* in_sizes, int n_in,
                              void* d_out, int out_size) {
    const float* x = nullptr; const float* Wg = nullptr; const float* bias = nullptr;
    for (int i = 0; i < n_in; i++) {
        if (in_sizes[i] == BATCH * SEQ * C_IN)   x    = (const float*)d_in[i];
        else if (in_sizes[i] == D_MODEL * KDIM)  Wg   = (const float*)d_in[i];
        else if (in_sizes[i] == D_MODEL)         bias = (const float*)d_in[i];
        // x_mark (BATCH*SEQ*4) unused by the reference math
    }
    float* out = (float*)d_out;

    dim3 g1(WPREP_BLOCKS, BATCH + 1);
    stats_kernel<<<g1, P1_TS>>>(x, Wg);

    cudaFuncSetAttribute(mma_kernel, cudaFuncAttributeMaxDynamicSharedMemorySize, SMEMB);
    dim3 g2((BATCH * SEQ) / BM, D_MODEL / BN, 1);
    mma_kernel<<<g2, CTH, SMEMB>>>(bias, out);
}

// round 16
// speedup vs baseline: 2.0906x; 1.1340x over previous
#include <cuda_runtime.h>
#include <cuda_fp16.h>
#include <math.h>
#include <stdint.h>

#define BATCH   32
#define SEQ     4096
#define C_IN    7
#define NF      35
#define D_MODEL 512
#define WINDOW  24
#define KDIM    105
#define FW      40           // F row width in halfs (80B, 16B-aligned)
#define FWU     20           // F row width in u32
#define LDW     128          // W row width in halfs in GMEM (K = 128, 8 k16 steps)
#define SLB     136          // W row stride in SMEM halfs (272B: conflict-free LDSM)
// F row = [35 feats | 5 zeros].  A row for output s = 120 contiguous halfs of
// g_F starting at (s-1)*40 (circular in s):  F[s-1] | F[s] | F[s+1].
// W col k: tap = k/40, i = k%40; real iff tap<3 && i<35, else zero.

// Compact padded fp16 feature rows: [BATCH*SEQ][40]
__device__ __align__(16) __half g_F[(size_t)BATCH * SEQ * FW];
// W reordered/padded fp16: [D_MODEL][128]
__device__ __align__(16) __half g_Wh[D_MODEL * LDW];

// ---------------------------------------------------------------------------
// Phase 1 (fused): rolling stats -> g_F;  W prep on the extra y-slice.
// ---------------------------------------------------------------------------
#define P1_TS 256
#define WPREP_BLOCKS ((D_MODEL * LDW) / P1_TS)   // 256
#define FST 21                                   // staging row stride (u32), coprime 32

__global__ __launch_bounds__(P1_TS) void stats_kernel(const float* __restrict__ x,
                                                      const float* __restrict__ Wg) {
    const int tid = threadIdx.x;

    if (blockIdx.y == BATCH) {
        // W prep: col k -> tap = k/40, i = k%40
        int idx = blockIdx.x * P1_TS + tid;
        int n = idx / LDW, k = idx - n * LDW;
        int tap = k / FW, i = k - tap * FW;
        float v = 0.0f;
        if (tap < 3 && i < NF) v = Wg[(size_t)n * KDIM + i * 3 + tap];
        g_Wh[idx] = __float2half(v);
        return;
    }
    if (blockIdx.x >= SEQ / P1_TS) return;

    __shared__ uint32_t fst[P1_TS * FST];                    // 21504 B
    __shared__ float sx[(P1_TS + WINDOW - 1) * C_IN];        //  7812 B

    const int b   = blockIdx.y;
    const int s0  = blockIdx.x * P1_TS;
    const float* xb = x + (size_t)b * SEQ * C_IN;

    for (int idx = tid; idx < (P1_TS + WINDOW - 1) * C_IN; idx += P1_TS) {
        int sg = s0 - (WINDOW - 1) + idx / C_IN;
        int c  = idx % C_IN;
        if (sg < 0) sg = 0;
        sx[idx] = xb[(size_t)sg * C_IN + c];
    }
    __syncthreads();

    float f[NF];
    #pragma unroll
    for (int c = 0; c < C_IN; c++) {
        float sum = 0.0f, mx = -3.0e38f, mn = 3.0e38f;
        #pragma unroll
        for (int t = 0; t < WINDOW; t++) {
            float v = sx[(tid + t) * C_IN + c];
            sum += v; mx = fmaxf(mx, v); mn = fminf(mn, v);
        }
        float mean = sum * (1.0f / WINDOW);
        float s2 = 0.0f;
        #pragma unroll
        for (int t = 0; t < WINDOW; t++) {
            float d = sx[(tid + t) * C_IN + c] - mean;
            s2 += d * d;
        }
        f[c]      = sx[(tid + WINDOW - 1) * C_IN + c];
        f[7 + c]  = mean;
        f[14 + c] = mx;
        f[21 + c] = mn;
        f[28 + c] = sqrtf(s2 * (1.0f / (WINDOW - 1)) + 1e-12f);
    }

    // pack & stage own row (stride 21 u32, coprime with 32 -> conflict-free)
    uint32_t* my = fst + tid * FST;
    #pragma unroll
    for (int i = 0; i < 17; i++) {
        __half2 h = __floats2half2_rn(f[2 * i], f[2 * i + 1]);
        my[i] = *(uint32_t*)&h;
    }
    {
        __half h = __float2half(f[34]);
        my[17] = (uint32_t)*(uint16_t*)&h;     // half 35 = 0
    }
    my[18] = 0; my[19] = 0;                    // halfs 36..39 = 0
    __syncthreads();

    // coalesced write: 256 rows x 20 u32 contiguous
    uint32_t* dst = (uint32_t*)g_F + ((size_t)b * SEQ + s0) * FWU;
    for (int idx = tid; idx < P1_TS * FWU; idx += P1_TS) {
        int r = idx / FWU, c = idx - r * FWU;
        dst[idx] = fst[r * FST + c];
    }
}

// ---------------------------------------------------------------------------
// Phase 2: fp16 mma.sync GEMM, full fp16 accumulation chain, K=128.
// CTA 128(M) x 128(N), 8 warps (2M x 4N), warp 64x32, 4 CTAs/SM.
// A = sliding-window view of 131 contiguous F rows; B at 136-half stride.
// Staged f16 epilogue -> coalesced STG.128.
// ---------------------------------------------------------------------------
#define BM 128
#define BN 128
#define CTH 256
#define FROWS 131
#define SF_U32 (FROWS * FWU + 4)                 // 2624 u32 = 10496 B
#define SMEMB (SF_U32 * 4 + BN * SLB * 2 + BN * 4)   // 10496+34816+512 = 45824
#define EST 68    // epilogue stage row stride (u32); 128 rows x 68 x 4 = 34816 B

__device__ __forceinline__ uint32_t smem_u32(const void* p) {
    uint32_t a;
    asm("{ .reg .u64 t; cvta.to.shared.u64 t, %1; cvt.u32.u64 %0, t; }" : "=r"(a) : "l"(p));
    return a;
}

__global__ __launch_bounds__(CTH, 4) void mma_kernel(const float* __restrict__ bias,
                                                     float* __restrict__ out) {
    extern __shared__ char smem[];
    uint32_t* sF  = (uint32_t*)smem;                     // 131 F-rows (20 u32 each)
    __half* sB    = (__half*)(smem + SF_U32 * 4);        // [BN][SLB]
    float*  sBias = (float*)(smem + SF_U32 * 4 + BN * SLB * 2);
    uint32_t* stage = (uint32_t*)smem;                   // reused post-mainloop

    const int tid = threadIdx.x;
    const int mt  = blockIdx.x;               // 1024 M-tiles
    const int b   = mt >> 5;                  // 32 tiles per batch
    const int s0  = (mt & 31) * BM;
    const int n0  = blockIdx.y * BN;

    // ---- A: contiguous circular copy of g_F rows s0-1 .. s0+129 ----
    {
        const uint32_t* Fu = (const uint32_t*)g_F + (size_t)b * SEQ * FWU;
        const int span = SEQ * FWU;            // 81920
        int base = (s0 - 1) * FWU;             // may be -20 (tile 0)
        for (int idx = tid; idx < FROWS * FWU; idx += CTH) {
            int lin = base + idx;
            if (lin < 0) lin += span;
            else if (lin >= span) lin -= span;
            sF[idx] = Fu[lin];
        }
        if (tid < 4) sF[FROWS * FWU + tid] = 0;
    }
    // ---- B: uint4 copy of W tile into 136-half-stride rows ----
    {
        const uint4* src = (const uint4*)(g_Wh + (size_t)n0 * LDW);
        for (int idx = tid; idx < BN * (LDW / 8); idx += CTH) {
            int r = idx >> 4, c = idx & 15;            // 16 uint4 per row
            *(uint4*)(sB + r * SLB + c * 8) = src[idx];
        }
    }
    if (tid < BN) sBias[tid] = bias[n0 + tid];
    __syncthreads();

    const int lane = tid & 31, w = tid >> 5;
    const int g = lane >> 2, q = lane & 3;
    const int mw = (w & 1) * 64;              // 2 warps along M (64 rows each)
    const int nw = (w >> 1) * 32;             // 4 warps along N (32 cols each)

    const uint32_t saBase = smem_u32(sF);
    const uint32_t sbBase = smem_u32(sB);
    const uint32_t aAddr = saBase +
        2u * ((uint32_t)(mw + (lane & 15)) * FW + ((lane >> 4) << 3));
    const uint32_t bt = lane >> 3, bj = lane & 7;
    const uint32_t bAddr = sbBase +
        2u * ((uint32_t)(nw + ((bt >> 1) << 3) + bj) * SLB + ((bt & 1) << 3));

    uint32_t d[4][4][2];
    #pragma unroll
    for (int mi = 0; mi < 4; mi++)
        #pragma unroll
        for (int ni = 0; ni < 4; ni++)
            d[mi][ni][0] = d[mi][ni][1] = 0u;

    #pragma unroll
    for (int ks = 0; ks < 8; ks++) {
        const uint32_t kOff = (uint32_t)ks * 32;   // bytes (16 halfs)

        uint32_t bf[4][2];
        #pragma unroll
        for (int nset = 0; nset < 2; nset++) {
            uint32_t ba = bAddr + kOff + (uint32_t)(nset * 16 * SLB * 2);
            asm volatile(
                "ldmatrix.sync.aligned.m8n8.x4.shared.b16 {%0,%1,%2,%3}, [%4];"
                : "=r"(bf[2 * nset][0]),     "=r"(bf[2 * nset][1]),
                  "=r"(bf[2 * nset + 1][0]), "=r"(bf[2 * nset + 1][1])
                : "r"(ba));
        }

        #pragma unroll
        for (int mi = 0; mi < 4; mi++) {
            uint32_t af[4];
            uint32_t aa = aAddr + (uint32_t)(2 * (mi * 16 * FW)) + kOff;
            asm volatile(
                "ldmatrix.sync.aligned.m8n8.x4.shared.b16 {%0,%1,%2,%3}, [%4];"
                : "=r"(af[0]), "=r"(af[1]), "=r"(af[2]), "=r"(af[3]) : "r"(aa));
            #pragma unroll
            for (int ni = 0; ni < 4; ni++)
                asm volatile(
                    "mma.sync.aligned.m16n8k16.row.col.f16.f16.f16.f16 "
                    "{%0,%1}, {%2,%3,%4,%5}, {%6,%7}, {%0,%1};"
                    : "+r"(d[mi][ni][0]), "+r"(d[mi][ni][1])
                    : "r"(af[0]), "r"(af[1]), "r"(af[2]), "r"(af[3]),
                      "r"(bf[ni][0]), "r"(bf[ni][1]));
        }
    }

    // ---- epilogue: stage f16 accumulators -> coalesced f32 stores ----
    float4 bv = *(const float4*)&sBias[lane * 4];   // this lane's 4 bias cols
    __syncthreads();                                // all LDSM done; reuse sF/sB

    // STS: addr = row*EST + colu;  lanes within an instr: (4g+q) mod 32 -> CF
    #pragma unroll
    for (int mi = 0; mi < 4; mi++)
        #pragma unroll
        for (int ni = 0; ni < 4; ni++) {
            uint32_t colu = (uint32_t)(nw / 2 + ni * 4 + q);
            uint32_t r0 = (uint32_t)(mw + mi * 16 + g);
            stage[r0 * EST + colu]       = d[mi][ni][0];
            stage[(r0 + 8) * EST + colu] = d[mi][ni][1];
        }
    __syncthreads();

    // 16 passes: warp w writes row p*8+w; lane covers 4 consecutive f32 cols
    float* obase = out + ((size_t)mt * BM) * D_MODEL + n0 + lane * 4;
    #pragma unroll
    for (int p = 0; p < 16; p++) {
        int row = p * 8 + w;
        uint2 pk = *(const uint2*)&stage[row * EST + lane * 2];
        float2 lo = __half22float2(*(__half2*)&pk.x);
        float2 hi = __half22float2(*(__half2*)&pk.y);
        float4 v = { lo.x + bv.x, lo.y + bv.y, hi.x + bv.z, hi.y + bv.w };
        *(float4*)(obase + (size_t)row * D_MODEL) = v;
    }
}

// ---------------------------------------------------------------------------
extern "C" void kernel_launch(void* const* d_in, const int* in_sizes, int n_in,
                              void* d_out, int out_size) {
    const float* x = nullptr; const float* Wg = nullptr; const float* bias = nullptr;
    for (int i = 0; i < n_in; i++) {
        if (in_sizes[i] == BATCH * SEQ * C_IN)   x    = (const float*)d_in[i];
        else if (in_sizes[i] == D_MODEL * KDIM)  Wg   = (const float*)d_in[i];
        else if (in_sizes[i] == D_MODEL)         bias = (const float*)d_in[i];
        // x_mark (BATCH*SEQ*4) unused by the reference math
    }
    float* out = (float*)d_out;

    dim3 g1(WPREP_BLOCKS, BATCH + 1);
    stats_kernel<<<g1, P1_TS>>>(x, Wg);

    cudaFuncSetAttribute(mma_kernel, cudaFuncAttributeMaxDynamicSharedMemorySize, SMEMB);
    dim3 g2((BATCH * SEQ) / BM, D_MODEL / BN, 1);
    mma_kernel<<<g2, CTH, SMEMB>>>(bias, out);
}

// round 17
// speedup vs baseline: 2.0988x; 1.0039x over previous
#include <cuda_runtime.h>
#include <cuda_fp16.h>
#include <math.h>
#include <stdint.h>

#define BATCH   32
#define SEQ     4096
#define C_IN    7
#define NF      35
#define D_MODEL 512
#define WINDOW  24
#define KDIM    105
#define FW      40           // F row width in halfs (80B, 16B-aligned)
#define FWU     20           // F row width in u32
#define LDW     128          // W row width in halfs in GMEM
#define SLB     136          // W row stride in SMEM halfs (272B: conflict-free LDSM)
// F row = [35 feats | 5 zeros].  A row for output s = 120 contiguous halfs of
// g_F starting at (s-1)*40 (circular in s):  F[s-1] | F[s] | F[s+1].
// W col k: tap = k/40, i = k%40; real iff tap<3 && i<35, else zero.
// K split: 7 x k16 steps (cols 0..111) + 1 x k8 tail (cols 112..119).

// Compact padded fp16 feature rows: [BATCH*SEQ][40]
__device__ __align__(16) __half g_F[(size_t)BATCH * SEQ * FW];
// W reordered/padded fp16: [D_MODEL][128]
__device__ __align__(16) __half g_Wh[D_MODEL * LDW];

// ---------------------------------------------------------------------------
// Phase 1 (fused): rolling stats -> g_F;  W prep on the extra y-slice.
// Channel-major x tile (lane-consecutive window loads) + one-pass moments.
// ---------------------------------------------------------------------------
#define P1_TS 256
#define WPREP_BLOCKS ((D_MODEL * LDW) / P1_TS)   // 256
#define SXR (P1_TS + WINDOW - 1)                 // 279 rows
#define FST 21                                   // staging row stride (u32), coprime 32

__global__ __launch_bounds__(P1_TS) void stats_kernel(const float* __restrict__ x,
                                                      const float* __restrict__ Wg) {
    const int tid = threadIdx.x;

    if (blockIdx.y == BATCH) {
        // W prep: col k -> tap = k/40, i = k%40
        int idx = blockIdx.x * P1_TS + tid;
        int n = idx / LDW, k = idx - n * LDW;
        int tap = k / FW, i = k - tap * FW;
        float v = 0.0f;
        if (tap < 3 && i < NF) v = Wg[(size_t)n * KDIM + i * 3 + tap];
        g_Wh[idx] = __float2half(v);
        return;
    }
    if (blockIdx.x >= SEQ / P1_TS) return;

    __shared__ uint32_t fst[P1_TS * FST];        // 21504 B
    __shared__ float sx[C_IN][SXR];              //  7812 B (channel-major)

    const int b   = blockIdx.y;
    const int s0  = blockIdx.x * P1_TS;
    const float* xb = x + (size_t)b * SEQ * C_IN;

    // gmem-linear load, transpose into channel-major smem
    for (int idx = tid; idx < SXR * C_IN; idx += P1_TS) {
        int l = idx / C_IN;                      // local row
        int c = idx - l * C_IN;
        int sg = s0 - (WINDOW - 1) + l;
        if (sg < 0) sg = 0;
        sx[c][l] = xb[(size_t)sg * C_IN + c];
    }
    __syncthreads();

    float f[NF];
    #pragma unroll
    for (int c = 0; c < C_IN; c++) {
        const float* base = &sx[c][tid];
        float s1 = 0.0f, s2 = 0.0f, mx = -3.0e38f, mn = 3.0e38f;
        float v = 0.0f;
        #pragma unroll
        for (int t = 0; t < WINDOW; t++) {
            v = base[t];
            s1 += v;
            s2 = fmaf(v, v, s2);
            mx = fmaxf(mx, v);
            mn = fminf(mn, v);
        }
        float mean = s1 * (1.0f / WINDOW);
        float var  = (s2 - s1 * s1 * (1.0f / WINDOW)) * (1.0f / (WINDOW - 1));
        f[c]      = v;                           // window's last = x[s]
        f[7 + c]  = mean;
        f[14 + c] = mx;
        f[21 + c] = mn;
        f[28 + c] = sqrtf(fmaxf(var, 0.0f) + 1e-12f);
    }

    // pack & stage own row (stride 21 u32, coprime with 32 -> conflict-free)
    uint32_t* my = fst + tid * FST;
    #pragma unroll
    for (int i = 0; i < 17; i++) {
        __half2 h = __floats2half2_rn(f[2 * i], f[2 * i + 1]);
        my[i] = *(uint32_t*)&h;
    }
    {
        __half h = __float2half(f[34]);
        my[17] = (uint32_t)*(uint16_t*)&h;       // half 35 = 0
    }
    my[18] = 0; my[19] = 0;                      // halfs 36..39 = 0
    __syncthreads();

    // coalesced write: 256 rows x 20 u32 contiguous
    uint32_t* dst = (uint32_t*)g_F + ((size_t)b * SEQ + s0) * FWU;
    for (int idx = tid; idx < P1_TS * FWU; idx += P1_TS) {
        int r = idx / FWU, c = idx - r * FWU;
        dst[idx] = fst[r * FST + c];
    }
}

// ---------------------------------------------------------------------------
// Phase 2: fp16 mma.sync GEMM, full fp16 accumulation chain.
// CTA 128(M) x 128(N), 8 warps (2M x 4N), warp 64x32, 4 CTAs/SM.
// 7 x k16 steps + 1 x k8 tail.  Staged f16 epilogue -> coalesced STG.128.
// ---------------------------------------------------------------------------
#define BM 128
#define BN 128
#define CTH 256
#define FROWS 131
#define SF_U32 (FROWS * FWU + 4)                 // 2624 u32 = 10496 B
#define SMEMB (SF_U32 * 4 + BN * SLB * 2 + BN * 4)   // 45824
#define EST 68    // epilogue stage row stride (u32)

__device__ __forceinline__ uint32_t smem_u32(const void* p) {
    uint32_t a;
    asm("{ .reg .u64 t; cvta.to.shared.u64 t, %1; cvt.u32.u64 %0, t; }" : "=r"(a) : "l"(p));
    return a;
}

__global__ __launch_bounds__(CTH, 4) void mma_kernel(const float* __restrict__ bias,
                                                     float* __restrict__ out) {
    extern __shared__ char smem[];
    uint32_t* sF  = (uint32_t*)smem;                     // 131 F-rows (20 u32 each)
    __half* sB    = (__half*)(smem + SF_U32 * 4);        // [BN][SLB]
    float*  sBias = (float*)(smem + SF_U32 * 4 + BN * SLB * 2);
    uint32_t* stage = (uint32_t*)smem;                   // reused post-mainloop

    const int tid = threadIdx.x;
    const int mt  = blockIdx.x;               // 1024 M-tiles
    const int b   = mt >> 5;                  // 32 tiles per batch
    const int s0  = (mt & 31) * BM;
    const int n0  = blockIdx.y * BN;

    // ---- A: contiguous circular copy of g_F rows s0-1 .. s0+129 ----
    {
        const uint32_t* Fu = (const uint32_t*)g_F + (size_t)b * SEQ * FWU;
        const int span = SEQ * FWU;            // 81920
        int base = (s0 - 1) * FWU;             // may be -20 (tile 0)
        for (int idx = tid; idx < FROWS * FWU; idx += CTH) {
            int lin = base + idx;
            if (lin < 0) lin += span;
            else if (lin >= span) lin -= span;
            sF[idx] = Fu[lin];
        }
        if (tid < 4) sF[FROWS * FWU + tid] = 0;
    }
    // ---- B: uint4 copy of W tile into 136-half-stride rows ----
    {
        const uint4* src = (const uint4*)(g_Wh + (size_t)n0 * LDW);
        for (int idx = tid; idx < BN * (LDW / 8); idx += CTH) {
            int r = idx >> 4, c = idx & 15;            // 16 uint4 per row
            *(uint4*)(sB + r * SLB + c * 8) = src[idx];
        }
    }
    if (tid < BN) sBias[tid] = bias[n0 + tid];
    __syncthreads();

    const int lane = tid & 31, w = tid >> 5;
    const int g = lane >> 2, q = lane & 3;
    const int mw = (w & 1) * 64;              // 2 warps along M (64 rows each)
    const int nw = (w >> 1) * 32;             // 4 warps along N (32 cols each)

    const uint32_t saBase = smem_u32(sF);
    const uint32_t sbBase = smem_u32(sB);
    const uint32_t aAddr = saBase +
        2u * ((uint32_t)(mw + (lane & 15)) * FW + ((lane >> 4) << 3));
    const uint32_t bt = lane >> 3, bj = lane & 7;
    const uint32_t bAddr = sbBase +
        2u * ((uint32_t)(nw + ((bt >> 1) << 3) + bj) * SLB + ((bt & 1) << 3));

    uint32_t d[4][4][2];
    #pragma unroll
    for (int mi = 0; mi < 4; mi++)
        #pragma unroll
        for (int ni = 0; ni < 4; ni++)
            d[mi][ni][0] = d[mi][ni][1] = 0u;

    // ---- 7 full k16 steps (cols 0..111) ----
    #pragma unroll
    for (int ks = 0; ks < 7; ks++) {
        const uint32_t kOff = (uint32_t)ks * 32;   // bytes (16 halfs)

        uint32_t bf[4][2];
        #pragma unroll
        for (int nset = 0; nset < 2; nset++) {
            uint32_t ba = bAddr + kOff + (uint32_t)(nset * 16 * SLB * 2);
            asm volatile(
                "ldmatrix.sync.aligned.m8n8.x4.shared.b16 {%0,%1,%2,%3}, [%4];"
                : "=r"(bf[2 * nset][0]),     "=r"(bf[2 * nset][1]),
                  "=r"(bf[2 * nset + 1][0]), "=r"(bf[2 * nset + 1][1])
                : "r"(ba));
        }

        #pragma unroll
        for (int mi = 0; mi < 4; mi++) {
            uint32_t af[4];
            uint32_t aa = aAddr + (uint32_t)(2 * (mi * 16 * FW)) + kOff;
            asm volatile(
                "ldmatrix.sync.aligned.m8n8.x4.shared.b16 {%0,%1,%2,%3}, [%4];"
                : "=r"(af[0]), "=r"(af[1]), "=r"(af[2]), "=r"(af[3]) : "r"(aa));
            #pragma unroll
            for (int ni = 0; ni < 4; ni++)
                asm volatile(
                    "mma.sync.aligned.m16n8k16.row.col.f16.f16.f16.f16 "
                    "{%0,%1}, {%2,%3,%4,%5}, {%6,%7}, {%0,%1};"
                    : "+r"(d[mi][ni][0]), "+r"(d[mi][ni][1])
                    : "r"(af[0]), "r"(af[1]), "r"(af[2]), "r"(af[3]),
                      "r"(bf[ni][0]), "r"(bf[ni][1]));
        }
    }

    // ---- k8 tail (cols 112..119): 1 B ldmatrix.x4 covers all 4 n-frags ----
    {
        uint32_t bfT[4];
        uint32_t baT = sbBase +
            2u * ((uint32_t)(nw + (bt << 3) + bj) * SLB + 112);
        asm volatile(
            "ldmatrix.sync.aligned.m8n8.x4.shared.b16 {%0,%1,%2,%3}, [%4];"
            : "=r"(bfT[0]), "=r"(bfT[1]), "=r"(bfT[2]), "=r"(bfT[3])
            : "r"(baT));
        #pragma unroll
        for (int mi = 0; mi < 4; mi++) {
            uint32_t afT[2];
            uint32_t aaT = saBase +
                2u * ((uint32_t)(mw + mi * 16 + (lane & 15)) * FW + 112);
            asm volatile(
                "ldmatrix.sync.aligned.m8n8.x2.shared.b16 {%0,%1}, [%2];"
                : "=r"(afT[0]), "=r"(afT[1]) : "r"(aaT));
            #pragma unroll
            for (int ni = 0; ni < 4; ni++)
                asm volatile(
                    "mma.sync.aligned.m16n8k8.row.col.f16.f16.f16.f16 "
                    "{%0,%1}, {%2,%3}, {%4}, {%0,%1};"
                    : "+r"(d[mi][ni][0]), "+r"(d[mi][ni][1])
                    : "r"(afT[0]), "r"(afT[1]), "r"(bfT[ni]));
        }
    }

    // ---- epilogue: stage f16 accumulators -> coalesced f32 stores ----
    float4 bv = *(const float4*)&sBias[lane * 4];   // this lane's 4 bias cols
    __syncthreads();                                // all LDSM done; reuse sF/sB

    #pragma unroll
    for (int mi = 0; mi < 4; mi++)
        #pragma unroll
        for (int ni = 0; ni < 4; ni++) {
            uint32_t colu = (uint32_t)(nw / 2 + ni * 4 + q);
            uint32_t r0 = (uint32_t)(mw + mi * 16 + g);
            stage[r0 * EST + colu]       = d[mi][ni][0];
            stage[(r0 + 8) * EST + colu] = d[mi][ni][1];
        }
    __syncthreads();

    float* obase = out + ((size_t)mt * BM) * D_MODEL + n0 + lane * 4;
    #pragma unroll
    for (int p = 0; p < 16; p++) {
        int row = p * 8 + w;
        uint2 pk = *(const uint2*)&stage[row * EST + lane * 2];
        float2 lo = __half22float2(*(__half2*)&pk.x);
        float2 hi = __half22float2(*(__half2*)&pk.y);
        float4 v = { lo.x + bv.x, lo.y + bv.y, hi.x + bv.z, hi.y + bv.w };
        *(float4*)(obase + (size_t)row * D_MODEL) = v;
    }
}

// ---------------------------------------------------------------------------
extern "C" void kernel_launch(void* const* d_in, const int* in_sizes, int n_in,
                              void* d_out, int out_size) {
    const float* x = nullptr; const float* Wg = nullptr; const float* bias = nullptr;
    for (int i = 0; i < n_in; i++) {
        if (in_sizes[i] == BATCH * SEQ * C_IN)   x    = (const float*)d_in[i];
        else if (in_sizes[i] == D_MODEL * KDIM)  Wg   = (const float*)d_in[i];
        else if (in_sizes[i] == D_MODEL)         bias = (const float*)d_in[i];
        // x_mark (BATCH*SEQ*4) unused by the reference math
    }
    float* out = (float*)d_out;

    dim3 g1(WPREP_BLOCKS, BATCH + 1);
    stats_kernel<<<g1, P1_TS>>>(x, Wg);

    cudaFuncSetAttribute(mma_kernel, cudaFuncAttributeMaxDynamicSharedMemorySize, SMEMB);
    dim3 g2((BATCH * SEQ) / BM, D_MODEL / BN, 1);
    mma_kernel<<<g2, CTH, SMEMB>>>(bias, out);
}